// round 1
// baseline (speedup 1.0000x reference)
#include <cuda_runtime.h>
#include <cuda_bf16.h>
#include <math.h>

#define S_LEN 2048
#define E_DIM 2048
#define HQ 32
#define HKV 8
#define D_HEAD 64
#define NKV (HKV * D_HEAD)   // 512

// ---------------- scratch (device globals; no allocs allowed) ----------------
__device__ float g_XQ[S_LEN * E_DIM];       // x @ Wq   [S, HQ*D]
__device__ float g_XK[S_LEN * NKV];         // x @ Wk   [S, HKV*D]
__device__ float g_XV[S_LEN * NKV];         // x @ Wv   [S, HKV*D]
__device__ float g_Q[HQ * S_LEN * D_HEAD];  // roped, [H][S][D]
__device__ float g_K[HKV * S_LEN * D_HEAD];
__device__ float g_V[HKV * S_LEN * D_HEAD];
__device__ float g_O[S_LEN * E_DIM];        // attention out [S, HQ*D]

// ---------------- SGEMM: C[M,N] = A[M,K] @ B[K,N], fp32 ----------------------
// 128x128 block tile, 16 K-tile, 256 threads, 8x8 per-thread microtile.
// Requires M%128==0, N%128==0, K%16==0 (true for all calls here).
#define TS 128
#define KT 16
__global__ __launch_bounds__(256) void sgemm_kernel(
    const float* __restrict__ A, const float* __restrict__ B,
    float* __restrict__ C, int M, int N, int K)
{
    __shared__ float As[KT][TS];
    __shared__ float Bs[KT][TS];

    const int tid = threadIdx.x;
    const int tx = tid & 15;       // N direction
    const int ty = tid >> 4;       // M direction
    const int bm = blockIdx.y * TS;
    const int bn = blockIdx.x * TS;

    float acc[8][8];
#pragma unroll
    for (int i = 0; i < 8; i++)
#pragma unroll
        for (int j = 0; j < 8; j++) acc[i][j] = 0.0f;

    for (int k0 = 0; k0 < K; k0 += KT) {
        // load A tile 128x16 (transposed into As[k][m])
#pragma unroll
        for (int r = 0; r < 2; r++) {
            int i = tid + r * 256;           // 0..511 float4 slots
            int row = i >> 2;                // 0..127
            int kc = (i & 3) * 4;            // 0,4,8,12
            float4 v = *(const float4*)(A + (size_t)(bm + row) * K + k0 + kc);
            As[kc + 0][row] = v.x;
            As[kc + 1][row] = v.y;
            As[kc + 2][row] = v.z;
            As[kc + 3][row] = v.w;
        }
        // load B tile 16x128 (direct)
#pragma unroll
        for (int r = 0; r < 2; r++) {
            int i = tid + r * 256;
            int row = i >> 5;                // 0..15
            int nc = (i & 31) * 4;           // 0..124
            *(float4*)(&Bs[row][nc]) =
                *(const float4*)(B + (size_t)(k0 + row) * N + bn + nc);
        }
        __syncthreads();

#pragma unroll
        for (int k = 0; k < KT; k++) {
            float a[8], b[8];
            *(float4*)(a)     = *(const float4*)(&As[k][ty * 8]);
            *(float4*)(a + 4) = *(const float4*)(&As[k][ty * 8 + 4]);
            *(float4*)(b)     = *(const float4*)(&Bs[k][tx * 8]);
            *(float4*)(b + 4) = *(const float4*)(&Bs[k][tx * 8 + 4]);
#pragma unroll
            for (int i = 0; i < 8; i++)
#pragma unroll
                for (int j = 0; j < 8; j++)
                    acc[i][j] = fmaf(a[i], b[j], acc[i][j]);
        }
        __syncthreads();
    }

#pragma unroll
    for (int i = 0; i < 8; i++) {
        int row = bm + ty * 8 + i;
        float* cp = C + (size_t)row * N + bn + tx * 8;
        *(float4*)(cp)     = make_float4(acc[i][0], acc[i][1], acc[i][2], acc[i][3]);
        *(float4*)(cp + 4) = make_float4(acc[i][4], acc[i][5], acc[i][6], acc[i][7]);
    }
}

// ---------------- RoPE + transpose to [H][S][D] ------------------------------
// head slots: 0..31 = Q heads (rope), 32..39 = K heads (rope), 40..47 = V heads (copy)
__global__ void rope_transpose_kernel(
    const float* __restrict__ fc,   // freqs_cis [S][32][2]
    float* __restrict__ Q, float* __restrict__ K, float* __restrict__ V)
{
    int idx = blockIdx.x * blockDim.x + threadIdx.x;
    const int total = S_LEN * 48 * 32;
    if (idx >= total) return;
    int pair = idx & 31;
    int hs = (idx >> 5) % 48;
    int s = idx / (48 * 32);

    float fr = fc[(size_t)s * 64 + pair * 2 + 0];
    float fi = fc[(size_t)s * 64 + pair * 2 + 1];

    if (hs < 32) {
        int h = hs;
        const float* src = g_XQ + (size_t)s * E_DIM + h * D_HEAD + pair * 2;
        float t0 = src[0], t1 = src[1];
        float* dst = Q + ((size_t)h * S_LEN + s) * D_HEAD + pair * 2;
        dst[0] = t0 * fr - t1 * fi;
        dst[1] = t0 * fi + t1 * fr;
    } else if (hs < 40) {
        int h = hs - 32;
        const float* src = g_XK + (size_t)s * NKV + h * D_HEAD + pair * 2;
        float t0 = src[0], t1 = src[1];
        float* dst = K + ((size_t)h * S_LEN + s) * D_HEAD + pair * 2;
        dst[0] = t0 * fr - t1 * fi;
        dst[1] = t0 * fi + t1 * fr;
    } else {
        int h = hs - 40;
        const float* src = g_XV + (size_t)s * NKV + h * D_HEAD + pair * 2;
        float* dst = V + ((size_t)h * S_LEN + s) * D_HEAD + pair * 2;
        dst[0] = src[0];
        dst[1] = src[1];
    }
}

// ---------------- flash-style causal GQA attention ---------------------------
// grid = (S/64 q-tiles, HQ heads), block = 64 threads, thread t owns query row
// q = qt*64+t. Q row & O accumulator in registers (float4[16] each).
// K/V tiles in smem (reads are warp-broadcast -> conflict free).
// S tile stored transposed Ss[j][t] for conflict-free stores/loads.
__global__ __launch_bounds__(64) void attn_kernel(
    const float* __restrict__ Qh, const float* __restrict__ Kh,
    const float* __restrict__ Vh, float* __restrict__ O)
{
    __shared__ float4 Ks[64][16];
    __shared__ float4 Vs[64][16];
    __shared__ float  Ss[64][64];   // [j][t]

    const int h = blockIdx.y;
    const int qt = blockIdx.x;
    const int t = threadIdx.x;
    const int q = qt * 64 + t;
    const int hk = h >> 2;          // REP = 4

    float4 qv[16], ov[16];
    const float4* qp = (const float4*)(Qh + ((size_t)h * S_LEN + q) * D_HEAD);
#pragma unroll
    for (int i = 0; i < 16; i++) qv[i] = qp[i];
#pragma unroll
    for (int i = 0; i < 16; i++) ov[i] = make_float4(0.f, 0.f, 0.f, 0.f);

    float m = -INFINITY, l = 0.0f;
    const float scale = 0.125f;     // 1/sqrt(64)

    for (int kt = 0; kt <= qt; kt++) {
        __syncthreads();
        {
            const float4* kp = (const float4*)(Kh + ((size_t)hk * S_LEN + kt * 64 + t) * D_HEAD);
            const float4* vp = (const float4*)(Vh + ((size_t)hk * S_LEN + kt * 64 + t) * D_HEAD);
#pragma unroll
            for (int i = 0; i < 16; i++) Ks[t][i] = kp[i];
#pragma unroll
            for (int i = 0; i < 16; i++) Vs[t][i] = vp[i];
        }
        __syncthreads();

        const int jmax = (kt == qt) ? t : 63;
        float mt = -INFINITY;
        for (int j = 0; j <= jmax; j++) {
            float s = 0.0f;
#pragma unroll
            for (int i = 0; i < 16; i++) {
                float4 kv = Ks[j][i];
                s = fmaf(qv[i].x, kv.x, s);
                s = fmaf(qv[i].y, kv.y, s);
                s = fmaf(qv[i].z, kv.z, s);
                s = fmaf(qv[i].w, kv.w, s);
            }
            s *= scale;
            Ss[j][t] = s;
            mt = fmaxf(mt, s);
        }

        float mnew = fmaxf(m, mt);
        float corr = __expf(m - mnew);
        l *= corr;
#pragma unroll
        for (int i = 0; i < 16; i++) {
            ov[i].x *= corr; ov[i].y *= corr; ov[i].z *= corr; ov[i].w *= corr;
        }
        m = mnew;

        for (int j = 0; j <= jmax; j++) {
            float p = __expf(Ss[j][t] - m);
            l += p;
#pragma unroll
            for (int i = 0; i < 16; i++) {
                float4 vv = Vs[j][i];
                ov[i].x = fmaf(p, vv.x, ov[i].x);
                ov[i].y = fmaf(p, vv.y, ov[i].y);
                ov[i].z = fmaf(p, vv.z, ov[i].z);
                ov[i].w = fmaf(p, vv.w, ov[i].w);
            }
        }
    }

    const float inv = 1.0f / l;
    float4* op = (float4*)(O + (size_t)q * E_DIM + h * D_HEAD);
#pragma unroll
    for (int i = 0; i < 16; i++) {
        float4 v = ov[i];
        op[i] = make_float4(v.x * inv, v.y * inv, v.z * inv, v.w * inv);
    }
}

// ---------------- launch -----------------------------------------------------
extern "C" void kernel_launch(void* const* d_in, const int* in_sizes, int n_in,
                              void* d_out, int out_size)
{
    const float* x  = (const float*)d_in[0];
    const float* fc = (const float*)d_in[1];
    // d_in[2] = mask (unused; causality implemented exactly)
    const float* Wq = (const float*)d_in[3];
    const float* Wk = (const float*)d_in[4];
    const float* Wv = (const float*)d_in[5];
    const float* Wo = (const float*)d_in[6];
    float* out = (float*)d_out;

    float *XQ, *XK, *XV, *Q, *K, *V, *O;
    cudaGetSymbolAddress((void**)&XQ, g_XQ);
    cudaGetSymbolAddress((void**)&XK, g_XK);
    cudaGetSymbolAddress((void**)&XV, g_XV);
    cudaGetSymbolAddress((void**)&Q,  g_Q);
    cudaGetSymbolAddress((void**)&K,  g_K);
    cudaGetSymbolAddress((void**)&V,  g_V);
    cudaGetSymbolAddress((void**)&O,  g_O);

    // QKV projections
    {
        dim3 g(E_DIM / TS, S_LEN / TS);
        sgemm_kernel<<<g, 256>>>(x, Wq, XQ, S_LEN, E_DIM, E_DIM);
    }
    {
        dim3 g(NKV / TS, S_LEN / TS);
        sgemm_kernel<<<g, 256>>>(x, Wk, XK, S_LEN, NKV, E_DIM);
        sgemm_kernel<<<g, 256>>>(x, Wv, XV, S_LEN, NKV, E_DIM);
    }

    // RoPE + transpose
    {
        int total = S_LEN * 48 * 32;
        rope_transpose_kernel<<<(total + 255) / 256, 256>>>(fc, Q, K, V);
    }

    // attention
    {
        dim3 g(S_LEN / 64, HQ);
        attn_kernel<<<g, 64>>>(Q, K, V, O);
    }

    // output projection
    {
        dim3 g(E_DIM / TS, S_LEN / TS);
        sgemm_kernel<<<g, 256>>>(O, Wo, out, S_LEN, E_DIM, E_DIM);
    }
}

// round 2
// speedup vs baseline: 3.3974x; 3.3974x over previous
#include <cuda_runtime.h>
#include <cuda_bf16.h>
#include <math.h>

#define S_LEN 2048
#define E_DIM 2048
#define HQ 32
#define HKV 8
#define D_HEAD 64
#define NKV (HKV * D_HEAD)   // 512

// ---------------- scratch (device globals; no allocs allowed) ----------------
__device__ float g_XQ[S_LEN * E_DIM];
__device__ float g_XK[S_LEN * NKV];
__device__ float g_XV[S_LEN * NKV];
__device__ float g_Q[HQ * S_LEN * D_HEAD];  // roped, [H][S][D]
__device__ float g_K[HKV * S_LEN * D_HEAD];
__device__ float g_V[HKV * S_LEN * D_HEAD];
__device__ float g_O[S_LEN * E_DIM];        // attention out [S, HQ*D]

// ---------------- tf32 helpers ----------------------------------------------
__device__ __forceinline__ unsigned f2tf(float x) {
    unsigned u;
    asm("cvt.rna.tf32.f32 %0, %1;" : "=r"(u) : "f"(x));
    return u;
}

__device__ __forceinline__ void mma_tf32(
    float& c0, float& c1, float& c2, float& c3,
    unsigned a0, unsigned a1, unsigned a2, unsigned a3,
    unsigned b0, unsigned b1)
{
    asm volatile(
        "mma.sync.aligned.m16n8k8.row.col.f32.tf32.tf32.f32 "
        "{%0,%1,%2,%3}, {%4,%5,%6,%7}, {%8,%9}, {%0,%1,%2,%3};\n"
        : "+f"(c0), "+f"(c1), "+f"(c2), "+f"(c3)
        : "r"(a0), "r"(a1), "r"(a2), "r"(a3), "r"(b0), "r"(b1));
}

// ---------------- tf32 tensor-core GEMM: C[M,N] = A[M,K] @ B[K,N] ------------
// 128x128 block, BK=32, 256 threads (8 warps), warp tile 64(M)x32(N).
#define BM 128
#define BN 128
#define BK 32
__global__ __launch_bounds__(256) void gemm_tf32_kernel(
    const float* __restrict__ A, const float* __restrict__ B,
    float* __restrict__ C, int M, int N, int K)
{
    __shared__ float As[BM][BK + 4];   // stride 36: frag banks 4r+c distinct
    __shared__ float Bs[BK][BN + 8];   // stride 136: frag banks 8r+c distinct

    const int tid = threadIdx.x;
    const int lane = tid & 31;
    const int warp = tid >> 5;
    const int wm = warp >> 2;          // 0..1  (M)
    const int wn = warp & 3;           // 0..3  (N)
    const int bm = blockIdx.y * BM;
    const int bn = blockIdx.x * BN;

    float acc[4][4][4];
#pragma unroll
    for (int i = 0; i < 4; i++)
#pragma unroll
        for (int j = 0; j < 4; j++)
#pragma unroll
            for (int r = 0; r < 4; r++) acc[i][j][r] = 0.0f;

    const int la = lane & 3;    // T%4
    const int lq = lane >> 2;   // T/4

    for (int k0 = 0; k0 < K; k0 += BK) {
        // A tile 128x32: 1024 float4 slots / 256 threads = 4 each
#pragma unroll
        for (int r = 0; r < 4; r++) {
            int slot = tid + r * 256;
            int row = slot >> 3;
            int kc4 = (slot & 7) * 4;
            float4 v = *(const float4*)(A + (size_t)(bm + row) * K + k0 + kc4);
            *(float4*)(&As[row][kc4]) = v;
        }
        // B tile 32x128
#pragma unroll
        for (int r = 0; r < 4; r++) {
            int slot = tid + r * 256;
            int row = slot >> 5;
            int nc = (slot & 31) * 4;
            float4 v = *(const float4*)(B + (size_t)(k0 + row) * N + bn + nc);
            *(float4*)(&Bs[row][nc]) = v;
        }
        __syncthreads();

#pragma unroll
        for (int kc = 0; kc < 4; kc++) {
            unsigned af[4][4], bf[4][2];
#pragma unroll
            for (int mt = 0; mt < 4; mt++) {
                int row = wm * 64 + mt * 16 + lq;
                int col = kc * 8 + la;
                af[mt][0] = f2tf(As[row][col]);
                af[mt][1] = f2tf(As[row + 8][col]);
                af[mt][2] = f2tf(As[row][col + 4]);
                af[mt][3] = f2tf(As[row + 8][col + 4]);
            }
#pragma unroll
            for (int nt = 0; nt < 4; nt++) {
                int col = wn * 32 + nt * 8 + lq;
                int row = kc * 8 + la;
                bf[nt][0] = f2tf(Bs[row][col]);
                bf[nt][1] = f2tf(Bs[row + 4][col]);
            }
#pragma unroll
            for (int mt = 0; mt < 4; mt++)
#pragma unroll
                for (int nt = 0; nt < 4; nt++)
                    mma_tf32(acc[mt][nt][0], acc[mt][nt][1], acc[mt][nt][2], acc[mt][nt][3],
                             af[mt][0], af[mt][1], af[mt][2], af[mt][3],
                             bf[nt][0], bf[nt][1]);
        }
        __syncthreads();
    }

#pragma unroll
    for (int mt = 0; mt < 4; mt++) {
#pragma unroll
        for (int nt = 0; nt < 4; nt++) {
            int row = bm + wm * 64 + mt * 16 + lq;
            int col = bn + wn * 32 + nt * 8 + 2 * la;
            *(float2*)(C + (size_t)row * N + col) =
                make_float2(acc[mt][nt][0], acc[mt][nt][1]);
            *(float2*)(C + (size_t)(row + 8) * N + col) =
                make_float2(acc[mt][nt][2], acc[mt][nt][3]);
        }
    }
}

// ---------------- RoPE + transpose to [H][S][D] ------------------------------
__global__ void rope_transpose_kernel(
    const float* __restrict__ fc,
    float* __restrict__ Q, float* __restrict__ K, float* __restrict__ V)
{
    int idx = blockIdx.x * blockDim.x + threadIdx.x;
    const int total = S_LEN * 48 * 32;
    if (idx >= total) return;
    int pair = idx & 31;
    int hs = (idx >> 5) % 48;
    int s = idx / (48 * 32);

    float fr = fc[(size_t)s * 64 + pair * 2 + 0];
    float fi = fc[(size_t)s * 64 + pair * 2 + 1];

    if (hs < 32) {
        int h = hs;
        const float* src = g_XQ + (size_t)s * E_DIM + h * D_HEAD + pair * 2;
        float t0 = src[0], t1 = src[1];
        float* dst = Q + ((size_t)h * S_LEN + s) * D_HEAD + pair * 2;
        dst[0] = t0 * fr - t1 * fi;
        dst[1] = t0 * fi + t1 * fr;
    } else if (hs < 40) {
        int h = hs - 32;
        const float* src = g_XK + (size_t)s * NKV + h * D_HEAD + pair * 2;
        float t0 = src[0], t1 = src[1];
        float* dst = K + ((size_t)h * S_LEN + s) * D_HEAD + pair * 2;
        dst[0] = t0 * fr - t1 * fi;
        dst[1] = t0 * fi + t1 * fr;
    } else {
        int h = hs - 40;
        const float* src = g_XV + (size_t)s * NKV + h * D_HEAD + pair * 2;
        float* dst = V + ((size_t)h * S_LEN + s) * D_HEAD + pair * 2;
        dst[0] = src[0];
        dst[1] = src[1];
    }
}

// ---------------- tensor-core flash attention (tf32) -------------------------
// grid (qt=S/64, h=HQ), 128 threads = 4 warps; warp w owns Q rows [w*16, w*16+16).
// S = Q@K^T and O += P@V via m16n8k8 tf32 mma. P accum->A-frag via shuffles.
#define KSTR 68   // Ks stride: banks 4*key + dim -> conflict-free for S B-frags
#define VSTR 72   // Vs stride: banks 8*key + dim -> conflict-free for PV B-frags
__global__ __launch_bounds__(128) void attn_kernel(
    const float* __restrict__ Qh, const float* __restrict__ Kh,
    const float* __restrict__ Vh, float* __restrict__ O)
{
    __shared__ float Ks[64][KSTR];
    __shared__ float Vs[64][VSTR];

    const int h = blockIdx.y;
    const int qt = blockIdx.x;
    const int tid = threadIdx.x;
    const int lane = tid & 31;
    const int warp = tid >> 5;
    const int hk = h >> 2;           // REP = 4
    const int q0 = qt * 64;
    const int la = lane & 3;
    const int lq = lane >> 2;

    // ---- stage Q tile through smem (coalesced), build A fragments ----
#pragma unroll
    for (int r = 0; r < 8; r++) {
        int slot = tid + r * 128;            // 1024 float4 slots
        int row = slot >> 4;
        int c4 = (slot & 15) * 4;
        *(float4*)(&Ks[row][c4]) =
            *(const float4*)(Qh + ((size_t)h * S_LEN + q0 + row) * D_HEAD + c4);
    }
    __syncthreads();

    unsigned qf[8][4];
#pragma unroll
    for (int kc = 0; kc < 8; kc++) {
        int row = warp * 16 + lq;
        int col = kc * 8 + la;
        qf[kc][0] = f2tf(Ks[row][col]);
        qf[kc][1] = f2tf(Ks[row + 8][col]);
        qf[kc][2] = f2tf(Ks[row][col + 4]);
        qf[kc][3] = f2tf(Ks[row + 8][col + 4]);
    }

    float o[8][4];
#pragma unroll
    for (int dt = 0; dt < 8; dt++)
#pragma unroll
        for (int r = 0; r < 4; r++) o[dt][r] = 0.0f;

    float m_lo = -INFINITY, m_hi = -INFINITY;
    float l_lo = 0.0f, l_hi = 0.0f;
    const float scale = 0.125f;

    const int s1 = (lane & ~3) | (la >> 1);   // src lane for cols T%4
    const int s2 = s1 + 2;                    // src lane for cols T%4+4
    const int odd = lane & 1;

    for (int kt = 0; kt <= qt; kt++) {
        __syncthreads();
#pragma unroll
        for (int r = 0; r < 8; r++) {
            int slot = tid + r * 128;
            int row = slot >> 4;
            int c4 = (slot & 15) * 4;
            *(float4*)(&Ks[row][c4]) =
                *(const float4*)(Kh + ((size_t)hk * S_LEN + kt * 64 + row) * D_HEAD + c4);
            *(float4*)(&Vs[row][c4]) =
                *(const float4*)(Vh + ((size_t)hk * S_LEN + kt * 64 + row) * D_HEAD + c4);
        }
        __syncthreads();

        // ---- S = Q @ K^T  (8 key-subtiles x 8 dim-chunks) ----
        float s[8][4];
#pragma unroll
        for (int nt = 0; nt < 8; nt++) {
            s[nt][0] = s[nt][1] = s[nt][2] = s[nt][3] = 0.0f;
#pragma unroll
            for (int kc = 0; kc < 8; kc++) {
                unsigned b0 = f2tf(Ks[nt * 8 + lq][kc * 8 + la]);
                unsigned b1 = f2tf(Ks[nt * 8 + lq][kc * 8 + la + 4]);
                mma_tf32(s[nt][0], s[nt][1], s[nt][2], s[nt][3],
                         qf[kc][0], qf[kc][1], qf[kc][2], qf[kc][3], b0, b1);
            }
        }

        // ---- scale + causal mask (diagonal tile only) ----
        float mt_lo = -INFINITY, mt_hi = -INFINITY;
#pragma unroll
        for (int nt = 0; nt < 8; nt++) {
#pragma unroll
            for (int r = 0; r < 4; r++) s[nt][r] *= scale;
            if (kt == qt) {
                int key0 = nt * 8 + 2 * la;
                int row_lo = warp * 16 + lq;
                int row_hi = row_lo + 8;
                if (key0     > row_lo) s[nt][0] = -1e30f;
                if (key0 + 1 > row_lo) s[nt][1] = -1e30f;
                if (key0     > row_hi) s[nt][2] = -1e30f;
                if (key0 + 1 > row_hi) s[nt][3] = -1e30f;
            }
            mt_lo = fmaxf(mt_lo, fmaxf(s[nt][0], s[nt][1]));
            mt_hi = fmaxf(mt_hi, fmaxf(s[nt][2], s[nt][3]));
        }
        // quad reduce (lanes sharing a row)
        mt_lo = fmaxf(mt_lo, __shfl_xor_sync(0xffffffffu, mt_lo, 1));
        mt_lo = fmaxf(mt_lo, __shfl_xor_sync(0xffffffffu, mt_lo, 2));
        mt_hi = fmaxf(mt_hi, __shfl_xor_sync(0xffffffffu, mt_hi, 1));
        mt_hi = fmaxf(mt_hi, __shfl_xor_sync(0xffffffffu, mt_hi, 2));

        float mn_lo = fmaxf(m_lo, mt_lo);
        float mn_hi = fmaxf(m_hi, mt_hi);
        float corr_lo = __expf(m_lo - mn_lo);
        float corr_hi = __expf(m_hi - mn_hi);
        m_lo = mn_lo; m_hi = mn_hi;
        l_lo *= corr_lo; l_hi *= corr_hi;
#pragma unroll
        for (int dt = 0; dt < 8; dt++) {
            o[dt][0] *= corr_lo; o[dt][1] *= corr_lo;
            o[dt][2] *= corr_hi; o[dt][3] *= corr_hi;
        }

        // ---- P = exp(S - m); row sums; convert to tf32 in place ----
        float ls_lo = 0.0f, ls_hi = 0.0f;
#pragma unroll
        for (int nt = 0; nt < 8; nt++) {
            float p0 = __expf(s[nt][0] - m_lo);
            float p1 = __expf(s[nt][1] - m_lo);
            float p2 = __expf(s[nt][2] - m_hi);
            float p3 = __expf(s[nt][3] - m_hi);
            ls_lo += p0 + p1;
            ls_hi += p2 + p3;
            s[nt][0] = __uint_as_float(f2tf(p0));
            s[nt][1] = __uint_as_float(f2tf(p1));
            s[nt][2] = __uint_as_float(f2tf(p2));
            s[nt][3] = __uint_as_float(f2tf(p3));
        }
        ls_lo += __shfl_xor_sync(0xffffffffu, ls_lo, 1);
        ls_lo += __shfl_xor_sync(0xffffffffu, ls_lo, 2);
        ls_hi += __shfl_xor_sync(0xffffffffu, ls_hi, 1);
        ls_hi += __shfl_xor_sync(0xffffffffu, ls_hi, 2);
        l_lo += ls_lo;
        l_hi += ls_hi;

        // ---- O += P @ V ; P accum-layout -> A-frag via quad shuffles ----
#pragma unroll
        for (int nt = 0; nt < 8; nt++) {   // nt = key chunk (k dimension)
            float v0 = __shfl_sync(0xffffffffu, s[nt][0], s1);
            float v1 = __shfl_sync(0xffffffffu, s[nt][1], s1);
            float v2 = __shfl_sync(0xffffffffu, s[nt][2], s1);
            float v3 = __shfl_sync(0xffffffffu, s[nt][3], s1);
            float w0 = __shfl_sync(0xffffffffu, s[nt][0], s2);
            float w1 = __shfl_sync(0xffffffffu, s[nt][1], s2);
            float w2 = __shfl_sync(0xffffffffu, s[nt][2], s2);
            float w3 = __shfl_sync(0xffffffffu, s[nt][3], s2);
            unsigned a0 = __float_as_uint(odd ? v1 : v0);
            unsigned a1 = __float_as_uint(odd ? v3 : v2);
            unsigned a2 = __float_as_uint(odd ? w1 : w0);
            unsigned a3 = __float_as_uint(odd ? w3 : w2);
#pragma unroll
            for (int dt = 0; dt < 8; dt++) {
                unsigned b0 = f2tf(Vs[nt * 8 + la][dt * 8 + lq]);
                unsigned b1 = f2tf(Vs[nt * 8 + la + 4][dt * 8 + lq]);
                mma_tf32(o[dt][0], o[dt][1], o[dt][2], o[dt][3],
                         a0, a1, a2, a3, b0, b1);
            }
        }
    }

    const float inv_lo = 1.0f / l_lo;
    const float inv_hi = 1.0f / l_hi;
    int row_lo = q0 + warp * 16 + lq;
    int row_hi = row_lo + 8;
#pragma unroll
    for (int dt = 0; dt < 8; dt++) {
        int col = h * D_HEAD + dt * 8 + 2 * la;
        *(float2*)(O + (size_t)row_lo * E_DIM + col) =
            make_float2(o[dt][0] * inv_lo, o[dt][1] * inv_lo);
        *(float2*)(O + (size_t)row_hi * E_DIM + col) =
            make_float2(o[dt][2] * inv_hi, o[dt][3] * inv_hi);
    }
}

// ---------------- launch -----------------------------------------------------
extern "C" void kernel_launch(void* const* d_in, const int* in_sizes, int n_in,
                              void* d_out, int out_size)
{
    const float* x  = (const float*)d_in[0];
    const float* fc = (const float*)d_in[1];
    const float* Wq = (const float*)d_in[3];
    const float* Wk = (const float*)d_in[4];
    const float* Wv = (const float*)d_in[5];
    const float* Wo = (const float*)d_in[6];
    float* out = (float*)d_out;

    float *XQ, *XK, *XV, *Q, *K, *V, *O;
    cudaGetSymbolAddress((void**)&XQ, g_XQ);
    cudaGetSymbolAddress((void**)&XK, g_XK);
    cudaGetSymbolAddress((void**)&XV, g_XV);
    cudaGetSymbolAddress((void**)&Q,  g_Q);
    cudaGetSymbolAddress((void**)&K,  g_K);
    cudaGetSymbolAddress((void**)&V,  g_V);
    cudaGetSymbolAddress((void**)&O,  g_O);

    {
        dim3 g(E_DIM / BN, S_LEN / BM);
        gemm_tf32_kernel<<<g, 256>>>(x, Wq, XQ, S_LEN, E_DIM, E_DIM);
    }
    {
        dim3 g(NKV / BN, S_LEN / BM);
        gemm_tf32_kernel<<<g, 256>>>(x, Wk, XK, S_LEN, NKV, E_DIM);
        gemm_tf32_kernel<<<g, 256>>>(x, Wv, XV, S_LEN, NKV, E_DIM);
    }
    {
        int total = S_LEN * 48 * 32;
        rope_transpose_kernel<<<(total + 255) / 256, 256>>>(fc, Q, K, V);
    }
    {
        dim3 g(S_LEN / 64, HQ);
        attn_kernel<<<g, 128>>>(Q, K, V, O);
    }
    {
        dim3 g(E_DIM / BN, S_LEN / BM);
        gemm_tf32_kernel<<<g, 256>>>(O, Wo, out, S_LEN, E_DIM, E_DIM);
    }
}

// round 3
// speedup vs baseline: 4.8826x; 1.4372x over previous
#include <cuda_runtime.h>
#include <cuda_bf16.h>
#include <math.h>

#define S_LEN 2048
#define E_DIM 2048
#define HQ 32
#define HKV 8
#define D_HEAD 64
#define NKV (HKV * D_HEAD)   // 512

// ---------------- scratch (device globals; no allocs allowed) ----------------
__device__ float g_XQ[S_LEN * E_DIM];
__device__ float g_XK[S_LEN * NKV];
__device__ float g_XV[S_LEN * NKV];
__device__ float g_Q[HQ * S_LEN * D_HEAD];  // roped, [H][S][D]
__device__ float g_K[HKV * S_LEN * D_HEAD];
__device__ float g_V[HKV * S_LEN * D_HEAD];
__device__ float g_O[S_LEN * E_DIM];        // attention out [S, HQ*D]

// ---------------- helpers ----------------------------------------------------
__device__ __forceinline__ unsigned f2tf(float x) {
    unsigned u;
    asm("cvt.rna.tf32.f32 %0, %1;" : "=r"(u) : "f"(x));
    return u;
}

__device__ __forceinline__ void mma_tf32(
    float& c0, float& c1, float& c2, float& c3,
    unsigned a0, unsigned a1, unsigned a2, unsigned a3,
    unsigned b0, unsigned b1)
{
    asm volatile(
        "mma.sync.aligned.m16n8k8.row.col.f32.tf32.tf32.f32 "
        "{%0,%1,%2,%3}, {%4,%5,%6,%7}, {%8,%9}, {%0,%1,%2,%3};\n"
        : "+f"(c0), "+f"(c1), "+f"(c2), "+f"(c3)
        : "r"(a0), "r"(a1), "r"(a2), "r"(a3), "r"(b0), "r"(b1));
}

__device__ __forceinline__ void cp_async16(void* sptr, const void* gptr) {
    unsigned saddr = (unsigned)__cvta_generic_to_shared(sptr);
    asm volatile("cp.async.cg.shared.global [%0], [%1], 16;\n"
                 :: "r"(saddr), "l"(gptr));
}
__device__ __forceinline__ void cp_commit() {
    asm volatile("cp.async.commit_group;\n");
}
template<int N> __device__ __forceinline__ void cp_wait() {
    asm volatile("cp.async.wait_group %0;\n" :: "n"(N));
}

// ---------------- pipelined tf32 GEMM core -----------------------------------
// 128x128 block, BK=32, 256 threads (8 warps), warp tile 64x32, 3-stage cp.async.
#define BM 128
#define BN 128
#define BK 32
#define ASTR (BK + 4)                 // 36
#define BSTR (BN + 8)                 // 136
#define A_ELEMS (BM * ASTR)           // 4608
#define B_ELEMS (BK * BSTR)           // 4352
#define G_STAGE (A_ELEMS + B_ELEMS)   // 8960 floats
#define G_SMEM (3 * G_STAGE * 4)      // 107520 bytes

__device__ __forceinline__ void gemm_issue(
    float* sm, int stage, const float* A, const float* B,
    int N, int K, int bm, int bn, int kt, int tid)
{
    float* As = sm + stage * G_STAGE;
    float* Bs = As + A_ELEMS;
    const int k0 = kt * BK;
#pragma unroll
    for (int r = 0; r < 4; r++) {
        int slot = tid + r * 256;
        int row = slot >> 3;
        int kc4 = (slot & 7) * 4;
        cp_async16(&As[row * ASTR + kc4], A + (size_t)(bm + row) * K + k0 + kc4);
    }
#pragma unroll
    for (int r = 0; r < 4; r++) {
        int slot = tid + r * 256;
        int row = slot >> 5;
        int nc = (slot & 31) * 4;
        cp_async16(&Bs[row * BSTR + nc], B + (size_t)(k0 + row) * N + bn + nc);
    }
}

__device__ __forceinline__ void gemm_core(
    const float* __restrict__ A, const float* __restrict__ B,
    float* __restrict__ C, int N, int K, int bm, int bn)
{
    extern __shared__ float sm[];
    const int tid = threadIdx.x;
    const int lane = tid & 31;
    const int warp = tid >> 5;
    const int wm = warp >> 2;
    const int wn = warp & 3;
    const int la = lane & 3;
    const int lq = lane >> 2;

    float acc[4][4][4];
#pragma unroll
    for (int i = 0; i < 4; i++)
#pragma unroll
        for (int j = 0; j < 4; j++)
#pragma unroll
            for (int r = 0; r < 4; r++) acc[i][j][r] = 0.0f;

    const int nt = K / BK;
    gemm_issue(sm, 0, A, B, N, K, bm, bn, 0, tid); cp_commit();
    gemm_issue(sm, 1, A, B, N, K, bm, bn, 1, tid); cp_commit();

    for (int kt = 0; kt < nt; kt++) {
        cp_wait<1>();
        __syncthreads();

        const float* As = sm + (kt % 3) * G_STAGE;
        const float* Bs = As + A_ELEMS;
#pragma unroll
        for (int kc = 0; kc < 4; kc++) {
            unsigned af[4][4], bf[4][2];
#pragma unroll
            for (int mt = 0; mt < 4; mt++) {
                int row = wm * 64 + mt * 16 + lq;
                int col = kc * 8 + la;
                af[mt][0] = f2tf(As[row * ASTR + col]);
                af[mt][1] = f2tf(As[(row + 8) * ASTR + col]);
                af[mt][2] = f2tf(As[row * ASTR + col + 4]);
                af[mt][3] = f2tf(As[(row + 8) * ASTR + col + 4]);
            }
#pragma unroll
            for (int ntb = 0; ntb < 4; ntb++) {
                int col = wn * 32 + ntb * 8 + lq;
                int row = kc * 8 + la;
                bf[ntb][0] = f2tf(Bs[row * BSTR + col]);
                bf[ntb][1] = f2tf(Bs[(row + 4) * BSTR + col]);
            }
#pragma unroll
            for (int mt = 0; mt < 4; mt++)
#pragma unroll
                for (int ntb = 0; ntb < 4; ntb++)
                    mma_tf32(acc[mt][ntb][0], acc[mt][ntb][1], acc[mt][ntb][2], acc[mt][ntb][3],
                             af[mt][0], af[mt][1], af[mt][2], af[mt][3],
                             bf[ntb][0], bf[ntb][1]);
        }
        __syncthreads();

        if (kt + 2 < nt)
            gemm_issue(sm, (kt + 2) % 3, A, B, N, K, bm, bn, kt + 2, tid);
        cp_commit();
    }

#pragma unroll
    for (int mt = 0; mt < 4; mt++) {
#pragma unroll
        for (int ntb = 0; ntb < 4; ntb++) {
            int row = bm + wm * 64 + mt * 16 + lq;
            int col = bn + wn * 32 + ntb * 8 + 2 * la;
            *(float2*)(C + (size_t)row * N + col) =
                make_float2(acc[mt][ntb][0], acc[mt][ntb][1]);
            *(float2*)(C + (size_t)(row + 8) * N + col) =
                make_float2(acc[mt][ntb][2], acc[mt][ntb][3]);
        }
    }
}

// fused QKV projections: blocks 0..255 -> Q, 256..319 -> K, 320..383 -> V
__global__ __launch_bounds__(256) void gemm_qkv_kernel(
    const float* __restrict__ x,
    const float* __restrict__ Wq, const float* __restrict__ Wk,
    const float* __restrict__ Wv,
    float* __restrict__ XQ, float* __restrict__ XK, float* __restrict__ XV)
{
    int bid = blockIdx.x;
    const float* B;
    float* C;
    int N, bm, bn;
    if (bid < 256) {
        B = Wq; C = XQ; N = E_DIM;
        bm = (bid >> 4) * BM; bn = (bid & 15) * BN;
    } else if (bid < 320) {
        int b = bid - 256;
        B = Wk; C = XK; N = NKV;
        bm = (b >> 2) * BM; bn = (b & 3) * BN;
    } else {
        int b = bid - 320;
        B = Wv; C = XV; N = NKV;
        bm = (b >> 2) * BM; bn = (b & 3) * BN;
    }
    gemm_core(x, B, C, N, E_DIM, bm, bn);
}

__global__ __launch_bounds__(256) void gemm_wo_kernel(
    const float* __restrict__ A, const float* __restrict__ B,
    float* __restrict__ C)
{
    gemm_core(A, B, C, E_DIM, E_DIM, blockIdx.y * BM, blockIdx.x * BN);
}

// ---------------- RoPE + transpose to [H][S][D] ------------------------------
__global__ void rope_transpose_kernel(
    const float* __restrict__ fc,
    float* __restrict__ Q, float* __restrict__ K, float* __restrict__ V)
{
    int idx = blockIdx.x * blockDim.x + threadIdx.x;
    const int total = S_LEN * 48 * 32;
    if (idx >= total) return;
    int pair = idx & 31;
    int hs = (idx >> 5) % 48;
    int s = idx / (48 * 32);

    float fr = fc[(size_t)s * 64 + pair * 2 + 0];
    float fi = fc[(size_t)s * 64 + pair * 2 + 1];

    if (hs < 32) {
        int h = hs;
        const float* src = g_XQ + (size_t)s * E_DIM + h * D_HEAD + pair * 2;
        float t0 = src[0], t1 = src[1];
        float* dst = Q + ((size_t)h * S_LEN + s) * D_HEAD + pair * 2;
        dst[0] = t0 * fr - t1 * fi;
        dst[1] = t0 * fi + t1 * fr;
    } else if (hs < 40) {
        int h = hs - 32;
        const float* src = g_XK + (size_t)s * NKV + h * D_HEAD + pair * 2;
        float t0 = src[0], t1 = src[1];
        float* dst = K + ((size_t)h * S_LEN + s) * D_HEAD + pair * 2;
        dst[0] = t0 * fr - t1 * fi;
        dst[1] = t0 * fi + t1 * fr;
    } else {
        int h = hs - 40;
        const float* src = g_XV + (size_t)s * NKV + h * D_HEAD + pair * 2;
        float* dst = V + ((size_t)h * S_LEN + s) * D_HEAD + pair * 2;
        dst[0] = src[0];
        dst[1] = src[1];
    }
}

// ---------------- pipelined tensor-core flash attention ----------------------
#define KSTR 68
#define VSTR 72
#define K_ELEMS (64 * KSTR)               // 4352
#define AT_STAGE (64 * KSTR + 64 * VSTR)  // 8960 floats
#define AT_SMEM (2 * AT_STAGE * 4)        // 71680 bytes

__device__ __forceinline__ void attn_issue(
    float* sm, int stage, const float* Kh, const float* Vh,
    int hk, int kt, int tid)
{
    float* ks = sm + stage * AT_STAGE;
    float* vs = ks + K_ELEMS;
#pragma unroll
    for (int r = 0; r < 8; r++) {
        int slot = tid + r * 128;
        int row = slot >> 4;
        int c4 = (slot & 15) * 4;
        const float* kp = Kh + ((size_t)hk * S_LEN + kt * 64 + row) * D_HEAD + c4;
        const float* vp = Vh + ((size_t)hk * S_LEN + kt * 64 + row) * D_HEAD + c4;
        cp_async16(&ks[row * KSTR + c4], kp);
        cp_async16(&vs[row * VSTR + c4], vp);
    }
}

__global__ __launch_bounds__(128) void attn_kernel(
    const float* __restrict__ Qh, const float* __restrict__ Kh,
    const float* __restrict__ Vh, float* __restrict__ O)
{
    extern __shared__ float sm[];

    const int h = blockIdx.y;
    const int qt = blockIdx.x;
    const int tid = threadIdx.x;
    const int lane = tid & 31;
    const int warp = tid >> 5;
    const int hk = h >> 2;
    const int q0 = qt * 64;
    const int la = lane & 3;
    const int lq = lane >> 2;

    // prologue: start KV tile 0 load into stage 0
    attn_issue(sm, 0, Kh, Vh, hk, 0, tid);
    cp_commit();

    // stage Q through stage-1 V region (free until loop iter 0 issues tile 1)
    float* qs = sm + AT_STAGE + K_ELEMS;
#pragma unroll
    for (int r = 0; r < 8; r++) {
        int slot = tid + r * 128;
        int row = slot >> 4;
        int c4 = (slot & 15) * 4;
        *(float4*)(&qs[row * KSTR + c4]) =
            *(const float4*)(Qh + ((size_t)h * S_LEN + q0 + row) * D_HEAD + c4);
    }
    __syncthreads();

    unsigned qf[8][4];
#pragma unroll
    for (int kc = 0; kc < 8; kc++) {
        int row = warp * 16 + lq;
        int col = kc * 8 + la;
        qf[kc][0] = f2tf(qs[row * KSTR + col]);
        qf[kc][1] = f2tf(qs[(row + 8) * KSTR + col]);
        qf[kc][2] = f2tf(qs[row * KSTR + col + 4]);
        qf[kc][3] = f2tf(qs[(row + 8) * KSTR + col + 4]);
    }
    __syncthreads();   // qf built before iter 0 overwrites stage 1

    float o[8][4];
#pragma unroll
    for (int dt = 0; dt < 8; dt++)
#pragma unroll
        for (int r = 0; r < 4; r++) o[dt][r] = 0.0f;

    float m_lo = -INFINITY, m_hi = -INFINITY;
    float l_lo = 0.0f, l_hi = 0.0f;
    const float scale = 0.125f;

    const int s1 = (lane & ~3) | (la >> 1);
    const int s2 = s1 + 2;
    const int odd = lane & 1;

    for (int kt = 0; kt <= qt; kt++) {
        if (kt + 1 <= qt)
            attn_issue(sm, (kt + 1) & 1, Kh, Vh, hk, kt + 1, tid);
        cp_commit();
        cp_wait<1>();
        __syncthreads();

        const float* ksp = sm + (kt & 1) * AT_STAGE;
        const float* vsp = ksp + K_ELEMS;

        // ---- S = Q @ K^T ----
        float s[8][4];
#pragma unroll
        for (int nt = 0; nt < 8; nt++) {
            s[nt][0] = s[nt][1] = s[nt][2] = s[nt][3] = 0.0f;
#pragma unroll
            for (int kc = 0; kc < 8; kc++) {
                unsigned b0 = f2tf(ksp[(nt * 8 + lq) * KSTR + kc * 8 + la]);
                unsigned b1 = f2tf(ksp[(nt * 8 + lq) * KSTR + kc * 8 + la + 4]);
                mma_tf32(s[nt][0], s[nt][1], s[nt][2], s[nt][3],
                         qf[kc][0], qf[kc][1], qf[kc][2], qf[kc][3], b0, b1);
            }
        }

        // ---- scale + causal mask ----
        float mt_lo = -INFINITY, mt_hi = -INFINITY;
#pragma unroll
        for (int nt = 0; nt < 8; nt++) {
#pragma unroll
            for (int r = 0; r < 4; r++) s[nt][r] *= scale;
            if (kt == qt) {
                int key0 = nt * 8 + 2 * la;
                int row_lo = warp * 16 + lq;
                int row_hi = row_lo + 8;
                if (key0     > row_lo) s[nt][0] = -1e30f;
                if (key0 + 1 > row_lo) s[nt][1] = -1e30f;
                if (key0     > row_hi) s[nt][2] = -1e30f;
                if (key0 + 1 > row_hi) s[nt][3] = -1e30f;
            }
            mt_lo = fmaxf(mt_lo, fmaxf(s[nt][0], s[nt][1]));
            mt_hi = fmaxf(mt_hi, fmaxf(s[nt][2], s[nt][3]));
        }
        mt_lo = fmaxf(mt_lo, __shfl_xor_sync(0xffffffffu, mt_lo, 1));
        mt_lo = fmaxf(mt_lo, __shfl_xor_sync(0xffffffffu, mt_lo, 2));
        mt_hi = fmaxf(mt_hi, __shfl_xor_sync(0xffffffffu, mt_hi, 1));
        mt_hi = fmaxf(mt_hi, __shfl_xor_sync(0xffffffffu, mt_hi, 2));

        float mn_lo = fmaxf(m_lo, mt_lo);
        float mn_hi = fmaxf(m_hi, mt_hi);
        float corr_lo = __expf(m_lo - mn_lo);
        float corr_hi = __expf(m_hi - mn_hi);
        m_lo = mn_lo; m_hi = mn_hi;
        l_lo *= corr_lo; l_hi *= corr_hi;
#pragma unroll
        for (int dt = 0; dt < 8; dt++) {
            o[dt][0] *= corr_lo; o[dt][1] *= corr_lo;
            o[dt][2] *= corr_hi; o[dt][3] *= corr_hi;
        }

        // ---- P = exp(S - m) ----
        float ls_lo = 0.0f, ls_hi = 0.0f;
#pragma unroll
        for (int nt = 0; nt < 8; nt++) {
            float p0 = __expf(s[nt][0] - m_lo);
            float p1 = __expf(s[nt][1] - m_lo);
            float p2 = __expf(s[nt][2] - m_hi);
            float p3 = __expf(s[nt][3] - m_hi);
            ls_lo += p0 + p1;
            ls_hi += p2 + p3;
            s[nt][0] = __uint_as_float(f2tf(p0));
            s[nt][1] = __uint_as_float(f2tf(p1));
            s[nt][2] = __uint_as_float(f2tf(p2));
            s[nt][3] = __uint_as_float(f2tf(p3));
        }
        ls_lo += __shfl_xor_sync(0xffffffffu, ls_lo, 1);
        ls_lo += __shfl_xor_sync(0xffffffffu, ls_lo, 2);
        ls_hi += __shfl_xor_sync(0xffffffffu, ls_hi, 1);
        ls_hi += __shfl_xor_sync(0xffffffffu, ls_hi, 2);
        l_lo += ls_lo;
        l_hi += ls_hi;

        // ---- O += P @ V ----
#pragma unroll
        for (int nt = 0; nt < 8; nt++) {
            float v0 = __shfl_sync(0xffffffffu, s[nt][0], s1);
            float v1 = __shfl_sync(0xffffffffu, s[nt][1], s1);
            float v2 = __shfl_sync(0xffffffffu, s[nt][2], s1);
            float v3 = __shfl_sync(0xffffffffu, s[nt][3], s1);
            float w0 = __shfl_sync(0xffffffffu, s[nt][0], s2);
            float w1 = __shfl_sync(0xffffffffu, s[nt][1], s2);
            float w2 = __shfl_sync(0xffffffffu, s[nt][2], s2);
            float w3 = __shfl_sync(0xffffffffu, s[nt][3], s2);
            unsigned a0 = __float_as_uint(odd ? v1 : v0);
            unsigned a1 = __float_as_uint(odd ? v3 : v2);
            unsigned a2 = __float_as_uint(odd ? w1 : w0);
            unsigned a3 = __float_as_uint(odd ? w3 : w2);
#pragma unroll
            for (int dt = 0; dt < 8; dt++) {
                unsigned b0 = f2tf(vsp[(nt * 8 + la) * VSTR + dt * 8 + lq]);
                unsigned b1 = f2tf(vsp[(nt * 8 + la + 4) * VSTR + dt * 8 + lq]);
                mma_tf32(o[dt][0], o[dt][1], o[dt][2], o[dt][3],
                         a0, a1, a2, a3, b0, b1);
            }
        }
        __syncthreads();   // reads done before next iter's issue overwrites
    }

    const float inv_lo = 1.0f / l_lo;
    const float inv_hi = 1.0f / l_hi;
    int row_lo = q0 + warp * 16 + lq;
    int row_hi = row_lo + 8;
#pragma unroll
    for (int dt = 0; dt < 8; dt++) {
        int col = h * D_HEAD + dt * 8 + 2 * la;
        *(float2*)(O + (size_t)row_lo * E_DIM + col) =
            make_float2(o[dt][0] * inv_lo, o[dt][1] * inv_lo);
        *(float2*)(O + (size_t)row_hi * E_DIM + col) =
            make_float2(o[dt][2] * inv_hi, o[dt][3] * inv_hi);
    }
}

// ---------------- launch -----------------------------------------------------
extern "C" void kernel_launch(void* const* d_in, const int* in_sizes, int n_in,
                              void* d_out, int out_size)
{
    const float* x  = (const float*)d_in[0];
    const float* fc = (const float*)d_in[1];
    const float* Wq = (const float*)d_in[3];
    const float* Wk = (const float*)d_in[4];
    const float* Wv = (const float*)d_in[5];
    const float* Wo = (const float*)d_in[6];
    float* out = (float*)d_out;

    float *XQ, *XK, *XV, *Q, *K, *V, *O;
    cudaGetSymbolAddress((void**)&XQ, g_XQ);
    cudaGetSymbolAddress((void**)&XK, g_XK);
    cudaGetSymbolAddress((void**)&XV, g_XV);
    cudaGetSymbolAddress((void**)&Q,  g_Q);
    cudaGetSymbolAddress((void**)&K,  g_K);
    cudaGetSymbolAddress((void**)&V,  g_V);
    cudaGetSymbolAddress((void**)&O,  g_O);

    cudaFuncSetAttribute(gemm_qkv_kernel,
                         cudaFuncAttributeMaxDynamicSharedMemorySize, G_SMEM);
    cudaFuncSetAttribute(gemm_wo_kernel,
                         cudaFuncAttributeMaxDynamicSharedMemorySize, G_SMEM);
    cudaFuncSetAttribute(attn_kernel,
                         cudaFuncAttributeMaxDynamicSharedMemorySize, AT_SMEM);

    gemm_qkv_kernel<<<384, 256, G_SMEM>>>(x, Wq, Wk, Wv, XQ, XK, XV);

    {
        int total = S_LEN * 48 * 32;
        rope_transpose_kernel<<<(total + 255) / 256, 256>>>(fc, Q, K, V);
    }

    {
        dim3 g(S_LEN / 64, HQ);
        attn_kernel<<<g, 128, AT_SMEM>>>(Q, K, V, O);
    }

    {
        dim3 g(E_DIM / BN, S_LEN / BM);
        gemm_wo_kernel<<<g, 256, G_SMEM>>>(O, Wo, out);
    }
}